// round 4
// baseline (speedup 1.0000x reference)
#include <cuda_runtime.h>
#include <math.h>

#define PB  128
#define PH  100
#define PC  32
#define PK  4
#define PD  400
#define PE  200
#define PCW 100
#define PN  (PB*PC)

#define DT   20                 // d-tile
#define HST  42                 // his dup row stride (floats): 2*DT + 2 pad, even
#define TILE_FLOATS (PH*HST + DT*PE)   // 4200 + 4000 = 8200 floats = 32.8KB

typedef unsigned long long ull;

__device__ __align__(16) float u_g[PB*PK*PD];
__device__ __align__(16) float uW_g[PB*PK*PE];

// ---- packed fp32x2 helpers ----
__device__ __forceinline__ ull pack2(float a, float b) {
    ull r; asm("mov.b64 %0, {%1, %2};" : "=l"(r) : "f"(a), "f"(b)); return r;
}
__device__ __forceinline__ void unpack2(ull v, float& a, float& b) {
    asm("mov.b64 {%0, %1}, %2;" : "=f"(a), "=f"(b) : "l"(v));
}
__device__ __forceinline__ void fma2(ull& d, ull a, ull b) {
    asm("fma.rn.f32x2 %0, %1, %2, %0;" : "+l"(d) : "l"(a), "l"(b));
}
__device__ __forceinline__ float tanh_fast(float x) {
    return __fdividef(2.f, 1.f + __expf(-2.f * x)) - 1.f;
}

// ---- cp.async ----
__device__ __forceinline__ unsigned smem_u32(const void* p) {
    return (unsigned)__cvta_generic_to_shared(p);
}
__device__ __forceinline__ void cp16(float* dst, const float* src) {
    asm volatile("cp.async.cg.shared.global [%0], [%1], 16;"
                 :: "r"(smem_u32(dst)), "l"(src));
}
__device__ __forceinline__ void cp_commit() {
    asm volatile("cp.async.commit_group;");
}
template <int N>
__device__ __forceinline__ void cp_wait() {
    asm volatile("cp.async.wait_group %0;" :: "n"(N));
}

// -----------------------------------------------------------------------------
// Kernel A: one block per (b,k).
// his tile stored DUPLICATED: hs[h*HST + 2dd] = hs[..+2dd+1] = his[h][d0+dd],
// so x loads are single LDS.64 broadcasts already in (x,x) form -> no MOV dups.
// Inner loop per dd: 10 LDS.64(x) + 4 LDS.64(w) + 40 FFMA2.
// -----------------------------------------------------------------------------
__global__ void __launch_bounds__(256, 2) kernelA(
    const float* __restrict__ his,
    const float* __restrict__ W_att, const float* __restrict__ b_att,
    const float* __restrict__ q_att, const float* __restrict__ W_lin,
    const float* __restrict__ b_lin)
{
    extern __shared__ float sm[];   // 2 * TILE_FLOATS
    __shared__ float s_s[PH];
    __shared__ float u_s[PD];
    __shared__ float red_s[2];

    const int bk = blockIdx.x;
    const int b  = bk >> 2;
    const int k  = bk & 3;
    const int tid = threadIdx.x;
    const int ty = tid / 25;          // 0..9 valid
    const int tx = tid - ty*25;       // 0..24
    const bool act = (tid < 250);

    for (int i = tid; i < PH; i += 256) s_s[i] = 0.f;

    const float* hisB = his + ((size_t)b*PH)*(PK*PD) + (size_t)k*PD;
    const float* WB   = W_att + (size_t)k*PD*PE;

    // his LDG stage: 1000 float2 units per tile; unit u: h=u/10, c=u%10
    float2 st[4];
    auto ldg_his = [&](int d0) {
        #pragma unroll
        for (int t = 0; t < 4; ++t) {
            int u = tid + t*256;
            if (u < 1000) {
                int h = u / 10, c = u - h*10;
                st[t] = *(const float2*)(hisB + (size_t)h*(PK*PD) + d0 + 2*c);
            }
        }
    };
    auto sts_his = [&](int buf) {
        float* hs = sm + buf*TILE_FLOATS;
        #pragma unroll
        for (int t = 0; t < 4; ++t) {
            int u = tid + t*256;
            if (u < 1000) {
                int h = u / 10, c = u - h*10;
                *(ull*)(hs + h*HST + 4*c)     = pack2(st[t].x, st[t].x);
                *(ull*)(hs + h*HST + 4*c + 2) = pack2(st[t].y, st[t].y);
            }
        }
    };
    auto cp_W = [&](int buf, int d0) {
        float* ws = sm + buf*TILE_FLOATS + PH*HST;
        const float* wsrc = WB + (size_t)d0*PE;
        #pragma unroll
        for (int t = 0; t < 4; ++t) {
            int u = tid + t*256;
            if (u < 1000) cp16(ws + u*4, wsrc + u*4);
        }
    };

    ull acc[10][4];
    #pragma unroll
    for (int r = 0; r < 10; ++r)
        #pragma unroll
        for (int j = 0; j < 4; ++j) acc[r][j] = 0ull;

    // prologue: tile 0
    ldg_his(0);
    cp_W(0, 0);
    cp_commit();
    sts_his(0);
    cp_wait<0>();
    __syncthreads();

    for (int dt = 0; dt < PD/DT; ++dt) {
        const int buf = dt & 1;
        if (dt < PD/DT - 1) {
            cp_W(buf ^ 1, (dt+1)*DT);
            cp_commit();
            ldg_his((dt+1)*DT);
        }

        if (act) {
            const float* hs = sm + buf*TILE_FLOATS;
            const float* ws = hs + PH*HST;
            const float* xbase = hs + ty*10*HST;
            const float* wbase = ws + tx*2;
            #pragma unroll 4
            for (int dd = 0; dd < DT; ++dd) {
                ull wv[4];
                const float* wrow = wbase + dd*PE;
                #pragma unroll
                for (int j = 0; j < 4; ++j)
                    wv[j] = *(const ull*)(wrow + j*50);
                #pragma unroll
                for (int r = 0; r < 10; ++r) {
                    ull xv = *(const ull*)(xbase + r*HST + 2*dd);
                    #pragma unroll
                    for (int j = 0; j < 4; ++j)
                        fma2(acc[r][j], xv, wv[j]);
                }
            }
        }

        if (dt < PD/DT - 1) {
            sts_his(buf ^ 1);
            cp_wait<0>();
        }
        __syncthreads();
    }

    // epilogue: s[h] += sum_e q*tanh(z + b_att)
    if (act) {
        float qa[8], ba[8];
        #pragma unroll
        for (int j = 0; j < 4; ++j) {
            const int e = 2*(tx + 25*j);
            qa[2*j]   = q_att[k*PE + e];     qa[2*j+1] = q_att[k*PE + e + 1];
            ba[2*j]   = b_att[k*PE + e];     ba[2*j+1] = b_att[k*PE + e + 1];
        }
        #pragma unroll
        for (int r = 0; r < 10; ++r) {
            float p = 0.f;
            #pragma unroll
            for (int j = 0; j < 4; ++j) {
                float z0, z1; unpack2(acc[r][j], z0, z1);
                p += qa[2*j]   * tanh_fast(z0 + ba[2*j]);
                p += qa[2*j+1] * tanh_fast(z1 + ba[2*j+1]);
            }
            atomicAdd(&s_s[ty*10 + r], p);
        }
    }
    __syncthreads();

    // softmax over h
    if (tid < 32) {
        float m = -1e30f;
        for (int h = tid; h < PH; h += 32) m = fmaxf(m, s_s[h]);
        #pragma unroll
        for (int off = 16; off; off >>= 1)
            m = fmaxf(m, __shfl_xor_sync(0xffffffffu, m, off));
        if (tid == 0) { red_s[0] = m; red_s[1] = 0.f; }
    }
    __syncthreads();
    const float mx = red_s[0];
    if (tid < PH) {
        float ex = __expf(s_s[tid] - mx);
        s_s[tid] = ex;
        atomicAdd(&red_s[1], ex);
    }
    __syncthreads();
    const float inv = 1.f / red_s[1];

    // u[d] = inv * sum_h ex[h]*his[h,d]
    for (int d = tid; d < PD; d += 256) {
        float a0 = 0.f, a1 = 0.f;
        #pragma unroll 4
        for (int h = 0; h < PH; h += 2) {
            a0 += s_s[h]   * hisB[(size_t)h*(PK*PD) + d];
            a1 += s_s[h+1] * hisB[(size_t)(h+1)*(PK*PD) + d];
        }
        float u = (a0 + a1) * inv;
        u_s[d] = u;
        u_g[bk*PD + d] = u;
    }
    __syncthreads();

    // uW[e] = b_lin[e] + sum_d u[d]*W_lin[d,e]
    for (int e = tid; e < PE; e += 256) {
        float a0 = b_lin[e], a1 = 0.f, a2 = 0.f, a3 = 0.f;
        #pragma unroll 2
        for (int d = 0; d < PD; d += 4) {
            a0 += u_s[d]   * W_lin[(d)*PE + e];
            a1 += u_s[d+1] * W_lin[(d+1)*PE + e];
            a2 += u_s[d+2] * W_lin[(d+2)*PE + e];
            a3 += u_s[d+3] * W_lin[(d+3)*PE + e];
        }
        uW_g[bk*PE + e] = (a0 + a1) + (a2 + a3);
    }
}

// -----------------------------------------------------------------------------
// Kernel CD: per block = 64 rows (g=(n,k)) = 16 n of one b.
//  sk = sum_e q_vec*tanh(uW + cwt@W_lin2)  (GEMM, FFMA2)
//  then softmax over k, dots u.cdd, scores, and u_channel broadcast copy.
// -----------------------------------------------------------------------------
__global__ void __launch_bounds__(256) kernelCD(
    const float* __restrict__ cwt, const float* __restrict__ W_lin,
    const float* __restrict__ q_vec, const float* __restrict__ cdd,
    float* __restrict__ out_scores, float* __restrict__ out_u)
{
    extern __shared__ float sm[];
    float* W2   = sm;                  // 100*200
    float* cw   = W2 + PCW*PE;         // 64*100
    float* u_sh = cw + 64*PCW;         // 4*400
    float* sk_s = u_sh + PK*PD;        // 64
    float* dt_s = sk_s + 64;           // 64

    const int tid = threadIdx.x;
    const int tx = tid & 7;
    const int ty = tid >> 3;
    const int row0 = blockIdx.x * 64;
    const int n0   = row0 >> 2;        // 16 n per block
    const int b    = n0 >> 5;          // single b per block

    for (int i = tid; i < PCW*PE; i += 256) W2[i] = W_lin[PD*PE + i];
    for (int i = tid; i < 64*PCW; i += 256) cw[i] = cwt[(size_t)row0*PCW + i];
    for (int i = tid; i < PK*PD; i += 256) u_sh[i] = u_g[b*PK*PD + i];
    __syncthreads();

    ull acc2[2][12];
    float accS[2] = {0.f, 0.f};
    #pragma unroll
    for (int r = 0; r < 2; ++r)
        #pragma unroll
        for (int j = 0; j < 12; ++j) acc2[r][j] = 0ull;

    const float* c0p = cw + (ty*2)*PCW;
    const float* c1p = c0p + PCW;

    #pragma unroll 2
    for (int f = 0; f < PCW; ++f) {
        const float c0 = c0p[f], c1 = c1p[f];
        const ull cc0 = pack2(c0, c0), cc1 = pack2(c1, c1);
        const float* wrow = W2 + f*PE + tx*2;
        #pragma unroll
        for (int j = 0; j < 12; ++j) {
            ull w2v = *(const ull*)(wrow + j*16);
            fma2(acc2[0][j], cc0, w2v);
            fma2(acc2[1][j], cc1, w2v);
        }
        const float wl = W2[f*PE + 192 + tx];
        accS[0] += c0 * wl;
        accS[1] += c1 * wl;
    }

    #pragma unroll
    for (int rr = 0; rr < 2; ++rr) {
        const int gl = ty*2 + rr;            // local row
        const int kk = (row0 + gl) & 3;
        const float* uWp = uW_g + ((b << 2) + kk)*PE;
        float p = 0.f;
        #pragma unroll
        for (int j = 0; j < 12; ++j) {
            const int e = j*16 + tx*2;
            float z0, z1; unpack2(acc2[rr][j], z0, z1);
            p += q_vec[e]     * tanh_fast(z0 + uWp[e]);
            p += q_vec[e + 1] * tanh_fast(z1 + uWp[e + 1]);
        }
        {
            const int e = 192 + tx;
            p += q_vec[e] * tanh_fast(accS[rr] + uWp[e]);
        }
        p += __shfl_xor_sync(0xffffffffu, p, 1);
        p += __shfl_xor_sync(0xffffffffu, p, 2);
        p += __shfl_xor_sync(0xffffffffu, p, 4);
        if (tx == 0) sk_s[gl] = p;
    }
    __syncthreads();

    // dots: one warp per local row, 8 warps -> 8 iterations
    {
        const int warp = tid >> 5, lane = tid & 31;
        const float4* u4 = (const float4*)u_sh;
        for (int gl = warp; gl < 64; gl += 8) {
            const int g = row0 + gl;
            const int n = g >> 2, kk = g & 3;
            const float4* c4 = (const float4*)(cdd + ((size_t)n*PK + kk)*PD);
            float a = 0.f;
            for (int i = lane; i < PD/4; i += 32) {
                float4 cv = c4[i];
                float4 uv = u4[kk*(PD/4) + i];
                a += cv.x*uv.x + cv.y*uv.y + cv.z*uv.z + cv.w*uv.w;
            }
            #pragma unroll
            for (int off = 16; off; off >>= 1)
                a += __shfl_xor_sync(0xffffffffu, a, off);
            if (lane == 0) dt_s[gl] = a;
        }
    }
    __syncthreads();

    if (tid < 16) {
        const int base = tid*4;
        const float s0 = sk_s[base], s1 = sk_s[base+1], s2 = sk_s[base+2], s3 = sk_s[base+3];
        const float m = fmaxf(fmaxf(s0, s1), fmaxf(s2, s3));
        const float w0 = __expf(s0 - m), w1 = __expf(s1 - m);
        const float w2 = __expf(s2 - m), w3 = __expf(s3 - m);
        out_scores[n0 + tid] =
            (w0*dt_s[base] + w1*dt_s[base+1] + w2*dt_s[base+2] + w3*dt_s[base+3])
            / (w0 + w1 + w2 + w3);
    }

    // u_channel broadcast: 16 n x 1600 floats
    {
        const float4* u4 = (const float4*)u_sh;
        float4* o4 = (float4*)(out_u + (size_t)n0*PK*PD);
        for (int idx = tid; idx < 16*(PK*PD/4); idx += 256) {
            int nn = idx / (PK*PD/4), i = idx - nn*(PK*PD/4);
            o4[(size_t)nn*(PK*PD/4) + i] = u4[i];
        }
    }
}

extern "C" void kernel_launch(void* const* d_in, const int* in_sizes, int n_in,
                              void* d_out, int out_size)
{
    const float* his   = (const float*)d_in[0];
    const float* cdd   = (const float*)d_in[1];
    const float* cwt   = (const float*)d_in[2];
    const float* W_att = (const float*)d_in[3];
    const float* b_att = (const float*)d_in[4];
    const float* q_att = (const float*)d_in[5];
    const float* W_lin = (const float*)d_in[6];
    const float* b_lin = (const float*)d_in[7];
    const float* q_vec = (const float*)d_in[8];
    float* out = (float*)d_out;
    (void)in_sizes; (void)n_in; (void)out_size;

    const int smemA = 2 * TILE_FLOATS * (int)sizeof(float);
    cudaFuncSetAttribute(kernelA, cudaFuncAttributeMaxDynamicSharedMemorySize, smemA);
    kernelA<<<PB*PK, 256, smemA>>>(his, W_att, b_att, q_att, W_lin, b_lin);

    const int smemCD = (PCW*PE + 64*PCW + PK*PD + 64 + 64) * (int)sizeof(float);
    cudaFuncSetAttribute(kernelCD, cudaFuncAttributeMaxDynamicSharedMemorySize, smemCD);
    kernelCD<<<(PN*PK)/64, 256, smemCD>>>(cwt, W_lin, q_vec, cdd, out, out + PN);
}

// round 5
// speedup vs baseline: 1.2458x; 1.2458x over previous
#include <cuda_runtime.h>
#include <cuda_fp16.h>
#include <math.h>

#define PB  128
#define PH  100
#define PC  32
#define PK  4
#define PD  400
#define PE  200
#define PCW 100
#define PN  (PB*PC)

// kernelA tiling
#define KPAD 448
#define KC   64          // k per chunk
#define NCH  7           // chunks
#define AS   72          // A smem row stride (halves)
#define BS   72          // B smem row stride (halves)
#define MROWS 128
#define BROWS 208        // 200 + 8 pad rows (zero)

#define A_PLANE (MROWS*AS)     // 9216 halves
#define B_PLANE (BROWS*BS)     // 14976 halves
#define SMEMA_HALVES (2*A_PLANE + 2*B_PLANE)   // 48384 halves = 96768 B

typedef unsigned long long ull;
typedef unsigned int uint;

__device__ __align__(16) float u_g[PB*PK*PD];
__device__ __align__(16) float uW_g[PB*PK*PE];
__device__ __align__(16) float sk_g[PN*PK];
__device__ unsigned work_ctr;

// ---- packed fp32x2 helpers (kernelC) ----
__device__ __forceinline__ ull pack2(float a, float b) {
    ull r; asm("mov.b64 %0, {%1, %2};" : "=l"(r) : "f"(a), "f"(b)); return r;
}
__device__ __forceinline__ void unpack2(ull v, float& a, float& b) {
    asm("mov.b64 {%0, %1}, %2;" : "=f"(a), "=f"(b) : "l"(v));
}
__device__ __forceinline__ void fma2(ull& d, ull a, ull b) {
    asm("fma.rn.f32x2 %0, %1, %2, %0;" : "+l"(d) : "l"(a), "l"(b));
}
__device__ __forceinline__ float tanh_fast(float x) {
    return __fdividef(2.f, 1.f + __expf(-2.f * x)) - 1.f;
}

// ---- mma.sync m16n8k16 f16 -> f32 ----
__device__ __forceinline__ void mma16816(
    float& c0, float& c1, float& c2, float& c3,
    uint a0, uint a1, uint a2, uint a3, uint b0, uint b1)
{
    asm volatile(
        "mma.sync.aligned.m16n8k16.row.col.f32.f16.f16.f32 "
        "{%0,%1,%2,%3}, {%4,%5,%6,%7}, {%8,%9}, {%0,%1,%2,%3};"
        : "+f"(c0), "+f"(c1), "+f"(c2), "+f"(c3)
        : "r"(a0), "r"(a1), "r"(a2), "r"(a3), "r"(b0), "r"(b1));
}

__device__ __forceinline__ ull pack4h(float x0, float x1, float x2, float x3) {
    __half2 h01 = __halves2half2(__float2half_rn(x0), __float2half_rn(x1));
    __half2 h23 = __halves2half2(__float2half_rn(x2), __float2half_rn(x3));
    uint u0 = *(uint*)&h01, u1 = *(uint*)&h23;
    return (ull)u0 | ((ull)u1 << 32);
}

__global__ void resetK() { work_ctr = 0; }

// -----------------------------------------------------------------------------
// Kernel A: persistent blocks, work-steal over 512 (b,k) items.
// Per item: z[100x200] = his_bk[100x400] @ W_att_k[400x200] via split-f16 MMA
// (3 mma per tile: AhBh + AhBl + AlBh; error ~2^-21). Then s/softmax/u/uW.
// 16 warps: warp w -> m-tile rows 16*(w>>1), n-half (w&1) of 13 tiles x 8 cols.
// -----------------------------------------------------------------------------
__global__ void __launch_bounds__(512, 1) kernelA(
    const float* __restrict__ his,
    const float* __restrict__ W_att, const float* __restrict__ b_att,
    const float* __restrict__ q_att, const float* __restrict__ W_lin,
    const float* __restrict__ b_lin)
{
    extern __shared__ __half smh[];
    __half* aHi = smh;
    __half* aLo = aHi + A_PLANE;
    __half* bHi = aLo + A_PLANE;
    __half* bLo = bHi + B_PLANE;

    __shared__ float s_s[PH];
    __shared__ float u_s[PD];
    __shared__ float qa_s[PE], ba_s[PE];
    __shared__ float red_s[2];
    __shared__ int item_s;

    const int tid  = threadIdx.x;
    const int warp = tid >> 5;
    const int lane = tid & 31;
    const int g    = lane >> 2;       // 0..7
    const int qq   = lane & 3;        // 0..3
    const int mrow0 = (warp >> 1) * 16;
    const int nbase = (warp & 1) * 104;   // 13 tiles * 8

    // zero B pad rows (200..207) once; loader never writes them
    for (int i = tid; i < 8*BS; i += 512) {
        bHi[200*BS + i] = __float2half(0.f);
        bLo[200*BS + i] = __float2half(0.f);
    }

    while (true) {
        if (tid == 0) item_s = (int)atomicAdd(&work_ctr, 1u);
        __syncthreads();
        const int bk = item_s;
        if (bk >= PB*PK) return;
        const int b = bk >> 2;
        const int k = bk & 3;

        const float* hisB = his + ((size_t)b*PH)*(PK*PD) + (size_t)k*PD;
        const float* WB   = W_att + (size_t)k*PD*PE;

        // per-item init
        for (int i = tid; i < PH; i += 512) s_s[i] = 0.f;
        for (int i = tid; i < PE; i += 512) {
            qa_s[i] = q_att[k*PE + i];
            ba_s[i] = b_att[k*PE + i];
        }

        float c[13][4];
        #pragma unroll
        for (int t = 0; t < 13; ++t)
            #pragma unroll
            for (int j = 0; j < 4; ++j) c[t][j] = 0.f;

        for (int ch = 0; ch < NCH; ++ch) {
            const int k0 = ch * KC;
            __syncthreads();   // previous compute done before overwrite

            // ---- load A: 128 rows x 64 k (f32 -> hi/lo halves) ----
            #pragma unroll
            for (int it = 0; it < 4; ++it) {
                int u = tid + it*512;                // 2048 float4 units
                int row = u >> 4, c4 = u & 15;
                int kg = k0 + c4*4;
                float4 v = make_float4(0.f, 0.f, 0.f, 0.f);
                if (row < PH && kg < PD)
                    v = *(const float4*)(hisB + (size_t)row*(PK*PD) + kg);
                float h0 = __half2float(__float2half_rn(v.x));
                float h1 = __half2float(__float2half_rn(v.y));
                float h2 = __half2float(__float2half_rn(v.z));
                float h3 = __half2float(__float2half_rn(v.w));
                *(ull*)(aHi + row*AS + c4*4) = pack4h(v.x, v.y, v.z, v.w);
                *(ull*)(aLo + row*AS + c4*4) = pack4h(v.x - h0, v.y - h1, v.z - h2, v.w - h3);
            }

            // ---- load B transposed: smem[n=e][k], 200 e x 64 k ----
            #pragma unroll
            for (int it = 0; it < 7; ++it) {
                int u = tid + it*512;                // 3200 units (4 k x 1 e)
                if (u < 3200) {
                    int kq = u / 200, e = u - kq*200;
                    float w[4];
                    #pragma unroll
                    for (int j = 0; j < 4; ++j) {
                        int kel = k0 + kq*4 + j;
                        w[j] = (kel < PD) ? WB[(size_t)kel*PE + e] : 0.f;
                    }
                    float h0 = __half2float(__float2half_rn(w[0]));
                    float h1 = __half2float(__float2half_rn(w[1]));
                    float h2 = __half2float(__float2half_rn(w[2]));
                    float h3 = __half2float(__float2half_rn(w[3]));
                    *(ull*)(bHi + e*BS + kq*4) = pack4h(w[0], w[1], w[2], w[3]);
                    *(ull*)(bLo + e*BS + kq*4) = pack4h(w[0]-h0, w[1]-h1, w[2]-h2, w[3]-h3);
                }
            }
            __syncthreads();

            // ---- compute: 4 k-steps of k16 ----
            #pragma unroll
            for (int ks = 0; ks < 4; ++ks) {
                const int kk = ks * 16;
                const int abase = (mrow0 + g)*AS + kk + qq*2;
                uint ah0 = *(const uint*)(aHi + abase);
                uint ah1 = *(const uint*)(aHi + abase + 8*AS);
                uint ah2 = *(const uint*)(aHi + abase + 8);
                uint ah3 = *(const uint*)(aHi + abase + 8*AS + 8);
                uint al0 = *(const uint*)(aLo + abase);
                uint al1 = *(const uint*)(aLo + abase + 8*AS);
                uint al2 = *(const uint*)(aLo + abase + 8);
                uint al3 = *(const uint*)(aLo + abase + 8*AS + 8);
                #pragma unroll
                for (int t = 0; t < 13; ++t) {
                    const int boff = (nbase + t*8 + g)*BS + kk + qq*2;
                    uint bh0 = *(const uint*)(bHi + boff);
                    uint bh1 = *(const uint*)(bHi + boff + 8);
                    uint bl0 = *(const uint*)(bLo + boff);
                    uint bl1 = *(const uint*)(bLo + boff + 8);
                    mma16816(c[t][0], c[t][1], c[t][2], c[t][3],
                             ah0, ah1, ah2, ah3, bh0, bh1);
                    mma16816(c[t][0], c[t][1], c[t][2], c[t][3],
                             ah0, ah1, ah2, ah3, bl0, bl1);
                    mma16816(c[t][0], c[t][1], c[t][2], c[t][3],
                             al0, al1, al2, al3, bh0, bh1);
                }
            }
        }
        __syncthreads();

        // ---- epilogue: s[h] += sum_e q*tanh(z + b_att) ----
        {
            const int r0 = mrow0 + g, r1 = r0 + 8;
            float p0 = 0.f, p1 = 0.f;
            #pragma unroll
            for (int t = 0; t < 13; ++t) {
                const int e0 = nbase + t*8 + qq*2;
                if (e0 < PE) {
                    const float q0 = qa_s[e0],   b0 = ba_s[e0];
                    const float q1 = qa_s[e0+1], b1 = ba_s[e0+1];
                    p0 += q0 * tanh_fast(c[t][0] + b0);
                    p0 += q1 * tanh_fast(c[t][1] + b1);
                    p1 += q0 * tanh_fast(c[t][2] + b0);
                    p1 += q1 * tanh_fast(c[t][3] + b1);
                }
            }
            if (r0 < PH) atomicAdd(&s_s[r0], p0);
            if (r1 < PH) atomicAdd(&s_s[r1], p1);
        }
        __syncthreads();

        // ---- softmax over h ----
        if (tid < 32) {
            float m = -1e30f;
            for (int h = tid; h < PH; h += 32) m = fmaxf(m, s_s[h]);
            #pragma unroll
            for (int off = 16; off; off >>= 1)
                m = fmaxf(m, __shfl_xor_sync(0xffffffffu, m, off));
            if (tid == 0) { red_s[0] = m; red_s[1] = 0.f; }
        }
        __syncthreads();
        const float mx = red_s[0];
        if (tid < PH) {
            float ex = __expf(s_s[tid] - mx);
            s_s[tid] = ex;
            atomicAdd(&red_s[1], ex);
        }
        __syncthreads();
        const float inv = 1.f / red_s[1];

        // ---- u[d] = inv * sum_h ex[h]*his[h,d] ----
        for (int d = tid; d < PD; d += 512) {
            float a0 = 0.f, a1 = 0.f;
            #pragma unroll 4
            for (int h = 0; h < PH; h += 2) {
                a0 += s_s[h]   * hisB[(size_t)h*(PK*PD) + d];
                a1 += s_s[h+1] * hisB[(size_t)(h+1)*(PK*PD) + d];
            }
            float uu = (a0 + a1) * inv;
            u_s[d] = uu;
            u_g[bk*PD + d] = uu;
        }
        __syncthreads();

        // ---- uW[e] = b_lin[e] + sum_d u[d]*W_lin[d,e] ----
        for (int e = tid; e < PE; e += 512) {
            float a0 = b_lin[e], a1 = 0.f, a2 = 0.f, a3 = 0.f;
            #pragma unroll 2
            for (int d = 0; d < PD; d += 4) {
                a0 += u_s[d]   * W_lin[(d)*PE + e];
                a1 += u_s[d+1] * W_lin[(d+1)*PE + e];
                a2 += u_s[d+2] * W_lin[(d+2)*PE + e];
                a3 += u_s[d+3] * W_lin[(d+3)*PE + e];
            }
            uW_g[bk*PE + e] = (a0 + a1) + (a2 + a3);
        }
        // loop: next item (loop-top barrier orders smem reuse)
    }
}

// -----------------------------------------------------------------------------
// Kernel C (R3): sk[n,k] = sum_e q_vec[e]*tanh(uW[b,k,e] + cwt[n,k,:]@W_lin2)
// -----------------------------------------------------------------------------
__global__ void __launch_bounds__(256) kernelC(
    const float* __restrict__ cwt, const float* __restrict__ W_lin,
    const float* __restrict__ q_vec)
{
    extern __shared__ float sm[];
    float* W2 = sm;             // 100*200
    float* cw = W2 + PCW*PE;    // 64*100

    const int tid = threadIdx.x;
    const int tx = tid & 7;
    const int ty = tid >> 3;
    const int row0 = blockIdx.x * 64;

    for (int i = tid; i < PCW*PE; i += 256) W2[i] = W_lin[PD*PE + i];
    for (int i = tid; i < 64*PCW; i += 256) cw[i] = cwt[(size_t)row0*PCW + i];
    __syncthreads();

    ull acc2[2][12];
    float accS[2] = {0.f, 0.f};
    #pragma unroll
    for (int r = 0; r < 2; ++r)
        #pragma unroll
        for (int j = 0; j < 12; ++j) acc2[r][j] = 0ull;

    const float* c0p = cw + (ty*2)*PCW;
    const float* c1p = c0p + PCW;

    #pragma unroll 2
    for (int f = 0; f < PCW; ++f) {
        const float c0 = c0p[f], c1 = c1p[f];
        const ull cc0 = pack2(c0, c0), cc1 = pack2(c1, c1);
        const float* wrow = W2 + f*PE + tx*2;
        #pragma unroll
        for (int j = 0; j < 12; ++j) {
            ull w2v = *(const ull*)(wrow + j*16);
            fma2(acc2[0][j], cc0, w2v);
            fma2(acc2[1][j], cc1, w2v);
        }
        const float wl = W2[f*PE + 192 + tx];
        accS[0] += c0 * wl;
        accS[1] += c1 * wl;
    }

    #pragma unroll
    for (int rr = 0; rr < 2; ++rr) {
        const int gidx = row0 + ty*2 + rr;
        const int n = gidx >> 2, kk = gidx & 3, b = n >> 5;
        const float* uWp = uW_g + ((b << 2) + kk)*PE;
        float p = 0.f;
        #pragma unroll
        for (int j = 0; j < 12; ++j) {
            const int e = j*16 + tx*2;
            float z0, z1; unpack2(acc2[rr][j], z0, z1);
            p += q_vec[e]     * tanh_fast(z0 + uWp[e]);
            p += q_vec[e + 1] * tanh_fast(z1 + uWp[e + 1]);
        }
        {
            const int e = 192 + tx;
            p += q_vec[e] * tanh_fast(accS[rr] + uWp[e]);
        }
        p += __shfl_xor_sync(0xffffffffu, p, 1);
        p += __shfl_xor_sync(0xffffffffu, p, 2);
        p += __shfl_xor_sync(0xffffffffu, p, 4);
        if (tx == 0) sk_g[gidx] = p;
    }
}

// -----------------------------------------------------------------------------
// Kernel D (R3): per n — softmax over sk[4], score, broadcast u_channel copy.
// -----------------------------------------------------------------------------
__global__ void __launch_bounds__(128) kernelD(
    const float* __restrict__ cdd,
    float* __restrict__ out_scores, float* __restrict__ out_u)
{
    const int n = blockIdx.x;
    const int b = n >> 5;
    const int tid = threadIdx.x;
    const int k = tid >> 5;
    const int lane = tid & 31;
    __shared__ float dot_s[4];

    const float* up = u_g + (size_t)((b << 2) + k)*PD;
    const float* cp = cdd + ((size_t)n*PK + k)*PD;
    float a = 0.f;
    for (int d = lane; d < PD; d += 32) a += up[d] * cp[d];
    #pragma unroll
    for (int off = 16; off; off >>= 1)
        a += __shfl_xor_sync(0xffffffffu, a, off);
    if (lane == 0) dot_s[k] = a;
    __syncthreads();

    if (tid == 0) {
        const float s0 = sk_g[n*4], s1 = sk_g[n*4+1], s2 = sk_g[n*4+2], s3 = sk_g[n*4+3];
        const float m = fmaxf(fmaxf(s0, s1), fmaxf(s2, s3));
        const float w0 = __expf(s0 - m), w1 = __expf(s1 - m);
        const float w2 = __expf(s2 - m), w3 = __expf(s3 - m);
        out_scores[n] = (w0*dot_s[0] + w1*dot_s[1] + w2*dot_s[2] + w3*dot_s[3])
                        / (w0 + w1 + w2 + w3);
    }

    const float4* u4 = (const float4*)(u_g + (size_t)b*PK*PD);
    float4* o4 = (float4*)(out_u + (size_t)n*PK*PD);
    #pragma unroll
    for (int i = tid; i < PK*PD/4; i += 128) o4[i] = u4[i];
}

extern "C" void kernel_launch(void* const* d_in, const int* in_sizes, int n_in,
                              void* d_out, int out_size)
{
    const float* his   = (const float*)d_in[0];
    const float* cdd   = (const float*)d_in[1];
    const float* cwt   = (const float*)d_in[2];
    const float* W_att = (const float*)d_in[3];
    const float* b_att = (const float*)d_in[4];
    const float* q_att = (const float*)d_in[5];
    const float* W_lin = (const float*)d_in[6];
    const float* b_lin = (const float*)d_in[7];
    const float* q_vec = (const float*)d_in[8];
    float* out = (float*)d_out;
    (void)in_sizes; (void)n_in; (void)out_size;

    resetK<<<1, 1>>>();

    const int smemA = SMEMA_HALVES * (int)sizeof(__half);   // 96768 B
    cudaFuncSetAttribute(kernelA, cudaFuncAttributeMaxDynamicSharedMemorySize, smemA);
    kernelA<<<148, 512, smemA>>>(his, W_att, b_att, q_att, W_lin, b_lin);

    const int smemC = (PCW*PE + 64*PCW) * (int)sizeof(float);
    cudaFuncSetAttribute(kernelC, cudaFuncAttributeMaxDynamicSharedMemorySize, smemC);
    kernelC<<<(PN*PK)/64, 256, smemC>>>(cwt, W_lin, q_vec);

    kernelD<<<PN, 128>>>(cdd, out, out + PN);
}